// round 1
// baseline (speedup 1.0000x reference)
#include <cuda_runtime.h>
#include <cuda_bf16.h>
#include <math.h>

// ---------------------------------------------------------------------------
// Llama-style decode step, BATCH=8, S=1, start_pos=2047.
// D_MODEL=4096, N_HEADS=32, N_KV=8, HEAD_DIM=128, HIDDEN=14336, VOCAB=32000.
// All matmuls are M=8 GEMVs -> HBM-bound. Split-K GEMM into partial buffers,
// deterministic combine kernels (no atomics).
// ---------------------------------------------------------------------------

#define DM 4096
#define NH 32
#define NKV 8
#define HD 128
#define HID 14336
#define VOC 32000
#define MSEQ 2048
#define B8 8

// ------------------------- scratch (device globals) -------------------------
__device__ float g_h[B8 * DM];        // residual stream
__device__ float g_xn[B8 * DM];       // rmsnorm output (reused)
__device__ float g_xq[B8 * NH * HD];
__device__ float g_xk[B8 * NKV * HD];
__device__ float g_xv[B8 * NKV * HD];
__device__ float g_pm[B8 * NH * 8];   // attention chunk max
__device__ float g_pl[B8 * NH * 8];   // attention chunk sumexp
__device__ float g_po[B8 * NH * 8 * HD]; // attention chunk weighted V
__device__ float g_attn[B8 * DM];
__device__ float g_g[B8 * HID];       // gated ffn activation
__device__ float g_bsq[B8 * 16];      // per-colblock sum of squares
__device__ float g_PA[64 * 8 * 4096]; // 2,097,152 floats: biggest partial buf
__device__ float g_PB[16 * 8 * 14336];// partial buf for w3

// ------------------------- helpers -------------------------
__device__ __forceinline__ void fma4(float4& a, float s, const float4& w) {
    a.x = fmaf(s, w.x, a.x);
    a.y = fmaf(s, w.y, a.y);
    a.z = fmaf(s, w.z, a.z);
    a.w = fmaf(s, w.w, a.w);
}

__device__ __forceinline__ float block_reduce_sum_256(float v) {
    __shared__ float red[8];
    int lane = threadIdx.x & 31, wid = threadIdx.x >> 5;
#pragma unroll
    for (int o = 16; o; o >>= 1) v += __shfl_xor_sync(0xffffffffu, v, o);
    if (!lane) red[wid] = v;
    __syncthreads();
    if (threadIdx.x == 0) {
        float t = 0.f;
#pragma unroll
        for (int w = 0; w < 8; ++w) t += red[w];
        red[0] = t;
    }
    __syncthreads();
    return red[0];
}

// ------------------------- kernel 0: embed + rmsnorm(gamma1) ----------------
__global__ void embed_norm(const int* __restrict__ tokens,
                           const float* __restrict__ emb,
                           const float* __restrict__ gamma) {
    int b = blockIdx.x;
    int tok = tokens[b];
    const float* row = emb + (size_t)tok * DM;
    float loc[16];
    float sq = 0.f;
#pragma unroll
    for (int i = 0; i < 16; ++i) {
        float v = row[threadIdx.x + i * 256];
        loc[i] = v;
        sq += v * v;
    }
    float tot = block_reduce_sum_256(sq);
    float rn = rsqrtf(tot * (1.0f / DM));
#pragma unroll
    for (int i = 0; i < 16; ++i) {
        int c = threadIdx.x + i * 256;
        g_h[b * DM + c] = loc[i];
        g_xn[b * DM + c] = loc[i] * rn * gamma[c];
    }
}

// ------------------------- generic split-K GEMM (M=8) -----------------------
// X[8,K] @ W[K,N] -> P[ks][8][N]. Threads map to 4 consecutive output columns
// (float4 loads of W, coalesced along N). 256 threads/block => 1024 cols/block.
// XSEL: 0 = g_xn, 1 = g_attn, 2 = g_g.  PSEL: 0 = g_PA, 1 = g_PB.
template <int XSEL, int PSEL>
__global__ void gemm8(const float* __restrict__ W, int K, int N, int kchunk) {
    const float* X = (XSEL == 0) ? g_xn : (XSEL == 1) ? g_attn : g_g;
    float* P = (PSEL == 0) ? g_PA : g_PB;

    __shared__ float4 xs[64][2]; // xs flattened: [kk][b], b packed in 2 float4

    int n0 = blockIdx.x * 1024 + threadIdx.x * 4;
    bool act = n0 < N;
    int k0 = blockIdx.y * kchunk;

    float4 acc[8];
#pragma unroll
    for (int b = 0; b < 8; ++b) acc[b] = make_float4(0.f, 0.f, 0.f, 0.f);

    for (int kt = 0; kt < kchunk; kt += 64) {
        __syncthreads();
        for (int i = threadIdx.x; i < 512; i += 256) {
            int b = i >> 6, kk = i & 63;
            ((float*)xs)[kk * 8 + b] = X[b * K + k0 + kt + kk];
        }
        __syncthreads();
        if (act) {
            const float* wp = W + (size_t)(k0 + kt) * N + n0;
#pragma unroll 4
            for (int kk = 0; kk < 64; ++kk) {
                float4 w = *(const float4*)wp;
                wp += N;
                float4 xa = xs[kk][0];
                float4 xb = xs[kk][1];
                fma4(acc[0], xa.x, w);
                fma4(acc[1], xa.y, w);
                fma4(acc[2], xa.z, w);
                fma4(acc[3], xa.w, w);
                fma4(acc[4], xb.x, w);
                fma4(acc[5], xb.y, w);
                fma4(acc[6], xb.z, w);
                fma4(acc[7], xb.w, w);
            }
        }
    }
    if (act) {
#pragma unroll
        for (int b = 0; b < 8; ++b) {
            *(float4*)(P + ((size_t)blockIdx.y * 8 + b) * N + n0) = acc[b];
        }
    }
}

// ------------------------- fused QKV GEMM (concat N=6144) -------------------
__global__ void gemm_qkv(const float* __restrict__ wq,
                         const float* __restrict__ wk,
                         const float* __restrict__ wv, int kchunk) {
    __shared__ float4 xs[64][2];
    const int K = DM;
    int nc = blockIdx.x * 1024 + threadIdx.x * 4; // concat column
    const float* W;
    int Nw, nl;
    if (nc < 4096) {
        W = wq; Nw = 4096; nl = nc;
    } else if (nc < 5120) {
        W = wk; Nw = 1024; nl = nc - 4096;
    } else {
        W = wv; Nw = 1024; nl = nc - 5120;
    }
    int k0 = blockIdx.y * kchunk;

    float4 acc[8];
#pragma unroll
    for (int b = 0; b < 8; ++b) acc[b] = make_float4(0.f, 0.f, 0.f, 0.f);

    for (int kt = 0; kt < kchunk; kt += 64) {
        __syncthreads();
        for (int i = threadIdx.x; i < 512; i += 256) {
            int b = i >> 6, kk = i & 63;
            ((float*)xs)[kk * 8 + b] = g_xn[b * K + k0 + kt + kk];
        }
        __syncthreads();
        const float* wp = W + (size_t)(k0 + kt) * Nw + nl;
#pragma unroll 4
        for (int kk = 0; kk < 64; ++kk) {
            float4 w = *(const float4*)wp;
            wp += Nw;
            float4 xa = xs[kk][0];
            float4 xb = xs[kk][1];
            fma4(acc[0], xa.x, w);
            fma4(acc[1], xa.y, w);
            fma4(acc[2], xa.z, w);
            fma4(acc[3], xa.w, w);
            fma4(acc[4], xb.x, w);
            fma4(acc[5], xb.y, w);
            fma4(acc[6], xb.z, w);
            fma4(acc[7], xb.w, w);
        }
    }
#pragma unroll
    for (int b = 0; b < 8; ++b) {
        *(float4*)(g_PA + ((size_t)blockIdx.y * 8 + b) * 6144 + nc) = acc[b];
    }
}

// --------------- QKV combine (sum 32 partials) + RoPE -----------------------
__global__ void qkv_finish(const int* __restrict__ sp) {
    int p = blockIdx.x * 256 + threadIdx.x; // 24576 pairs
    int b = p / 3072;
    int r = p - b * 3072;
    int c0 = r * 2;
    float s0 = 0.f, s1 = 0.f;
#pragma unroll 8
    for (int ks = 0; ks < 32; ++ks) {
        const float* pp = g_PA + ((size_t)ks * 8 + b) * 6144 + c0;
        s0 += pp[0];
        s1 += pp[1];
    }
    int pos = *sp;
    if (c0 < 4096) {
        int i = (c0 & 127) >> 1;
        float ifreq = powf(10000.0f, -(float)i * (1.0f / 64.0f));
        float ang = (float)pos * ifreq;
        float sn, cs;
        sincosf(ang, &sn, &cs);
        g_xq[b * 4096 + c0] = s0 * cs - s1 * sn;
        g_xq[b * 4096 + c0 + 1] = s0 * sn + s1 * cs;
    } else if (c0 < 5120) {
        int cc = c0 - 4096;
        int i = (cc & 127) >> 1;
        float ifreq = powf(10000.0f, -(float)i * (1.0f / 64.0f));
        float ang = (float)pos * ifreq;
        float sn, cs;
        sincosf(ang, &sn, &cs);
        g_xk[b * 1024 + cc] = s0 * cs - s1 * sn;
        g_xk[b * 1024 + cc + 1] = s0 * sn + s1 * cs;
    } else {
        int cc = c0 - 5120;
        g_xv[b * 1024 + cc] = s0;
        g_xv[b * 1024 + cc + 1] = s1;
    }
}

// --------------- attention: per (chunk, kv, b) partial softmax ---------------
// chunk = 256 seq positions; block handles the 4 query heads of one kv head.
__global__ void attn_part(const float* __restrict__ cache_k,
                          const float* __restrict__ cache_v,
                          const int* __restrict__ sp) {
    int chunk = blockIdx.x, kv = blockIdx.y, b = blockIdx.z;
    int pos = *sp;
    int L = pos + 1;
    int s0 = chunk * 256;
    int tid = threadIdx.x;

    __shared__ float4 qs[4][32];
    __shared__ float sc[4][256];
    __shared__ float red[4][8];
    __shared__ float Mh[4], Lh[4];

    for (int i = tid; i < 512; i += 256) {
        int j = i >> 7, d = i & 127;
        ((float*)qs)[j * 128 + d] = g_xq[((b << 5) + (kv << 2) + j) * 128 + d];
    }
    __syncthreads();

    int s = s0 + tid;
    bool valid = s < L;
    float d0, d1, d2, d3;
    if (valid) {
        const float* kr = (s == pos)
                              ? (g_xk + ((b << 3) + kv) * 128)
                              : (cache_k + ((size_t)(b * MSEQ + s)) * (NKV * HD) + kv * HD);
        d0 = d1 = d2 = d3 = 0.f;
        const float4* kr4 = (const float4*)kr;
#pragma unroll 8
        for (int q = 0; q < 32; ++q) {
            float4 k4 = kr4[q];
            float4 a = qs[0][q], bb = qs[1][q], c = qs[2][q], e = qs[3][q];
            d0 += k4.x * a.x + k4.y * a.y + k4.z * a.z + k4.w * a.w;
            d1 += k4.x * bb.x + k4.y * bb.y + k4.z * bb.z + k4.w * bb.w;
            d2 += k4.x * c.x + k4.y * c.y + k4.z * c.z + k4.w * c.w;
            d3 += k4.x * e.x + k4.y * e.y + k4.z * e.z + k4.w * e.w;
        }
        const float scale = 0.08838834764831845f; // 1/sqrt(128)
        d0 *= scale; d1 *= scale; d2 *= scale; d3 *= scale;
    } else {
        d0 = d1 = d2 = d3 = -1e30f;
    }

    float vals[4] = {d0, d1, d2, d3};
    int lane = tid & 31, wid = tid >> 5;
#pragma unroll
    for (int j = 0; j < 4; ++j) {
        float m = vals[j];
#pragma unroll
        for (int o = 16; o; o >>= 1) m = fmaxf(m, __shfl_xor_sync(0xffffffffu, m, o));
        if (!lane) red[j][wid] = m;
    }
    __syncthreads();
    if (tid < 4) {
        float m = red[tid][0];
#pragma unroll
        for (int w = 1; w < 8; ++w) m = fmaxf(m, red[tid][w]);
        Mh[tid] = m;
    }
    __syncthreads();
#pragma unroll
    for (int j = 0; j < 4; ++j) {
        float p = valid ? expf(vals[j] - Mh[j]) : 0.f;
        sc[j][tid] = p;
#pragma unroll
        for (int o = 16; o; o >>= 1) p += __shfl_xor_sync(0xffffffffu, p, o);
        if (!lane) red[j][wid] = p;
    }
    __syncthreads();
    if (tid < 4) {
        float t = 0.f;
#pragma unroll
        for (int w = 0; w < 8; ++w) t += red[tid][w];
        Lh[tid] = t;
    }
    __syncthreads();

    // weighted V accumulation: thread = (head-pair jj, dim d)
    int jj = tid >> 7, d = tid & 127;
    float a0 = 0.f, a1 = 0.f;
    int nvalid = min(256, L - s0);
    int ncache = min(nvalid, pos - s0);
    const float* vr = cache_v + ((size_t)(b * MSEQ + s0)) * (NKV * HD) + kv * HD + d;
    for (int ss = 0; ss < ncache; ++ss) {
        float v = *vr;
        vr += NKV * HD;
        a0 = fmaf(sc[jj][ss], v, a0);
        a1 = fmaf(sc[jj + 2][ss], v, a1);
    }
    if (pos >= s0 && pos < s0 + nvalid) {
        int ss = pos - s0;
        float v = g_xv[((b << 3) + kv) * 128 + d];
        a0 = fmaf(sc[jj][ss], v, a0);
        a1 = fmaf(sc[jj + 2][ss], v, a1);
    }
    int h0 = (kv << 2) + jj;
    g_po[(((size_t)(b << 5) + h0) * 8 + chunk) * 128 + d] = a0;
    g_po[(((size_t)(b << 5) + h0 + 2) * 8 + chunk) * 128 + d] = a1;
    if (tid < 4) {
        g_pm[((b << 5) + (kv << 2) + tid) * 8 + chunk] = Mh[tid];
        g_pl[((b << 5) + (kv << 2) + tid) * 8 + chunk] = Lh[tid];
    }
}

// --------------- attention: combine chunk partials ---------------------------
__global__ void attn_combine() {
    int h = blockIdx.x, b = blockIdx.y, d = threadIdx.x; // 128 threads
    int base = ((b << 5) + h) * 8;
    float M = -1e30f;
#pragma unroll
    for (int c = 0; c < 8; ++c) M = fmaxf(M, g_pm[base + c]);
    float Ls = 0.f, o = 0.f;
#pragma unroll
    for (int c = 0; c < 8; ++c) {
        float w = expf(g_pm[base + c] - M);
        Ls += g_pl[base + c] * w;
        o += g_po[(size_t)(base + c) * 128 + d] * w;
    }
    g_attn[((b << 5) + h) * 128 + d] = o / Ls;
}

// --------------- combine partials + residual; stash colblock sumsq ----------
__global__ void finish_res(int KS) {
    int b = blockIdx.y;
    int c = blockIdx.x * 256 + threadIdx.x; // grid.x = 16 -> 4096 cols
    float s = g_h[b * DM + c];
    for (int ks = 0; ks < KS; ++ks) s += g_PA[((size_t)ks * 8 + b) * DM + c];
    g_h[b * DM + c] = s;
    float tot = block_reduce_sum_256(s * s);
    if (threadIdx.x == 0) g_bsq[b * 16 + blockIdx.x] = tot;
}

// --------------- rmsnorm using stashed sums ---------------------------------
__global__ void finish_norm(const float* __restrict__ gamma) {
    int b = blockIdx.y;
    int c = blockIdx.x * 256 + threadIdx.x;
    float sq = 0.f;
#pragma unroll
    for (int i = 0; i < 16; ++i) sq += g_bsq[b * 16 + i];
    float rn = rsqrtf(sq * (1.0f / DM));
    g_xn[b * DM + c] = g_h[b * DM + c] * rn * gamma[c];
}

// --------------- ffn gate: g = silu(x@w1) * (x@w3) ---------------------------
__global__ void ffn_act(int KS) {
    int b = blockIdx.y;
    int c = blockIdx.x * 256 + threadIdx.x; // grid.x = 56 -> 14336
    float s1 = 0.f, s3 = 0.f;
    for (int ks = 0; ks < KS; ++ks) {
        s1 += g_PA[((size_t)ks * 8 + b) * HID + c];
        s3 += g_PB[((size_t)ks * 8 + b) * HID + c];
    }
    float sig = 1.0f / (1.0f + expf(-s1));
    g_g[b * HID + c] = s1 * sig * s3;
}

// --------------- logits combine ----------------------------------------------
__global__ void wout_finish(float* __restrict__ out, int KS) {
    int b = blockIdx.y;
    int c = blockIdx.x * 256 + threadIdx.x; // grid.x = 125 -> 32000
    float s = 0.f;
    for (int ks = 0; ks < KS; ++ks) s += g_PA[((size_t)ks * 8 + b) * VOC + c];
    out[b * VOC + c] = s;
}

// ------------------------- launch --------------------------------------------
extern "C" void kernel_launch(void* const* d_in, const int* in_sizes, int n_in,
                              void* d_out, int out_size) {
    const int* tokens = (const int*)d_in[0];
    const int* sp = (const int*)d_in[1];
    const float* emb = (const float*)d_in[2];
    const float* g1 = (const float*)d_in[3];
    const float* g2 = (const float*)d_in[4];
    const float* gf = (const float*)d_in[5];
    const float* wq = (const float*)d_in[6];
    const float* wk = (const float*)d_in[7];
    const float* wv = (const float*)d_in[8];
    const float* wo = (const float*)d_in[9];
    const float* w1 = (const float*)d_in[10];
    const float* w2 = (const float*)d_in[11];
    const float* w3 = (const float*)d_in[12];
    const float* wout = (const float*)d_in[13];
    const float* ck = (const float*)d_in[14];
    const float* cv = (const float*)d_in[15];
    float* out = (float*)d_out;

    // h, xn = embed + rmsnorm(gamma1)
    embed_norm<<<8, 256>>>(tokens, emb, g1);
    // QKV: K=4096, Ncat=6144, KS=32 (kchunk=128) -> 192 blocks
    gemm_qkv<<<dim3(6, 32), 256>>>(wq, wk, wv, 128);
    qkv_finish<<<96, 256>>>(sp);
    // attention: 8 chunks x 8 kv x 8 batch = 512 blocks
    attn_part<<<dim3(8, 8, 8), 256>>>(ck, cv, sp);
    attn_combine<<<dim3(32, 8), 128>>>();
    // wo: K=4096, N=4096, KS=64 (kchunk=64) -> 256 blocks; X = g_attn
    gemm8<1, 0><<<dim3(4, 64), 256>>>(wo, 4096, 4096, 64);
    finish_res<<<dim3(16, 8), 256>>>(64);
    finish_norm<<<dim3(16, 8), 256>>>(g2);
    // w1 / w3: K=4096, N=14336, KS=16 (kchunk=256) -> 224 blocks each
    gemm8<0, 0><<<dim3(14, 16), 256>>>(w1, 4096, 14336, 256);
    gemm8<0, 1><<<dim3(14, 16), 256>>>(w3, 4096, 14336, 256);
    ffn_act<<<dim3(56, 8), 256>>>(16);
    // w2: K=14336, N=4096, KS=56 (kchunk=256) -> 224 blocks; X = g_g
    gemm8<2, 0><<<dim3(4, 56), 256>>>(w2, 14336, 4096, 256);
    finish_res<<<dim3(16, 8), 256>>>(56);
    finish_norm<<<dim3(16, 8), 256>>>(gf);
    // w_out: K=4096, N=32000, KS=8 (kchunk=512) -> 256 blocks; X = g_xn
    gemm8<0, 0><<<dim3(32, 8), 256>>>(wout, 4096, 32000, 512);
    wout_finish<<<dim3(125, 8), 256>>>(out, 8);
}

// round 2
// speedup vs baseline: 1.1136x; 1.1136x over previous
#include <cuda_runtime.h>
#include <cuda_bf16.h>
#include <math.h>

// ---------------------------------------------------------------------------
// Llama-style decode step, BATCH=8, S=1. HBM-bound GEMVs with f32x2 packed
// FMA + flash-decode attention with coalesced K/V access.
// ---------------------------------------------------------------------------

#define DM 4096
#define NH 32
#define NKV 8
#define HD 128
#define HID 14336
#define VOC 32000
#define MSEQ 2048
#define B8 8
#define ACH 128   // attention chunk length
#define NCHK 16   // MSEQ / ACH

// ------------------------- scratch (device globals) -------------------------
__device__ float g_h[B8 * DM];
__device__ float g_xn[B8 * DM];
__device__ float g_xq[B8 * NH * HD];
__device__ float g_xk[B8 * NKV * HD];
__device__ float g_xv[B8 * NKV * HD];
__device__ float g_pm[B8 * NH * NCHK];
__device__ float g_pl[B8 * NH * NCHK];
__device__ float g_po[B8 * NH * NCHK * HD];
__device__ float g_attn[B8 * DM];
__device__ float g_g[B8 * HID];
__device__ float g_bsq[B8 * 16];
__device__ float g_PA[16 * 8 * 32000];   // 4.10M floats, largest partial buf
__device__ float g_PB[16 * 8 * 14336];

// ------------------------- helpers -------------------------
__device__ __forceinline__ void fma4(float4& a, float s, const float4& w) {
    a.x = fmaf(s, w.x, a.x);
    a.y = fmaf(s, w.y, a.y);
    a.z = fmaf(s, w.z, a.z);
    a.w = fmaf(s, w.w, a.w);
}

__device__ __forceinline__ float block_reduce_sum_256(float v) {
    __shared__ float red[8];
    int lane = threadIdx.x & 31, wid = threadIdx.x >> 5;
#pragma unroll
    for (int o = 16; o; o >>= 1) v += __shfl_xor_sync(0xffffffffu, v, o);
    if (!lane) red[wid] = v;
    __syncthreads();
    if (threadIdx.x == 0) {
        float t = 0.f;
#pragma unroll
        for (int w = 0; w < 8; ++w) t += red[w];
        red[0] = t;
    }
    __syncthreads();
    return red[0];
}

__device__ __forceinline__ unsigned long long dup_f32(float v) {
    unsigned long long pv;
    asm("mov.b64 %0, {%1, %1};" : "=l"(pv) : "f"(v));
    return pv;
}

// Core f32x2 inner step: acc pairs (cols c0c1, c2c3) x 8 batches.
#define F32X2_STEP(a01, a23, xp_lo, xp_hi, w_lo, w_hi)                         \
    asm("fma.rn.f32x2 %0, %4, %6, %0;\n\t"                                     \
        "fma.rn.f32x2 %1, %4, %7, %1;\n\t"                                     \
        "fma.rn.f32x2 %2, %5, %6, %2;\n\t"                                     \
        "fma.rn.f32x2 %3, %5, %7, %3;"                                         \
        : "+l"(a01##_e), "+l"(a23##_e), "+l"(a01##_o), "+l"(a23##_o)           \
        : "l"(xp_lo), "l"(xp_hi), "l"(w_lo), "l"(w_hi))

// ------------------------- kernel 0: embed + rmsnorm(gamma1) ----------------
__global__ void embed_norm(const int* __restrict__ tokens,
                           const float* __restrict__ emb,
                           const float* __restrict__ gamma) {
    int b = blockIdx.x;
    int tok = tokens[b];
    const float* row = emb + (size_t)tok * DM;
    float loc[16];
    float sq = 0.f;
#pragma unroll
    for (int i = 0; i < 16; ++i) {
        float v = row[threadIdx.x + i * 256];
        loc[i] = v;
        sq += v * v;
    }
    float tot = block_reduce_sum_256(sq);
    float rn = rsqrtf(tot * (1.0f / DM));
#pragma unroll
    for (int i = 0; i < 16; ++i) {
        int c = threadIdx.x + i * 256;
        g_h[b * DM + c] = loc[i];
        g_xn[b * DM + c] = loc[i] * rn * gamma[c];
    }
}

// ------------------------- generic split-K GEMM (M=8), f32x2 ----------------
// XSEL: 0 = g_xn, 1 = g_attn, 2 = g_g.  PSEL: 0 = g_PA, 1 = g_PB.
template <int XSEL, int PSEL>
__global__ void gemm8(const float* __restrict__ W, int K, int N, int kchunk) {
    const float* X = (XSEL == 0) ? g_xn : (XSEL == 1) ? g_attn : g_g;
    float* P = (PSEL == 0) ? g_PA : g_PB;

    __shared__ __align__(16) unsigned long long xs[64][8]; // dup'd x pairs

    int n0 = blockIdx.x * 1024 + threadIdx.x * 4;
    bool act = n0 < N;
    int k0 = blockIdx.y * kchunk;

    unsigned long long a01[8], a23[8];
#pragma unroll
    for (int b = 0; b < 8; ++b) { a01[b] = 0ull; a23[b] = 0ull; }

    for (int kt = 0; kt < kchunk; kt += 64) {
        __syncthreads();
        for (int i = threadIdx.x; i < 512; i += 256) {
            int kk = i >> 3, b = i & 7;
            xs[kk][b] = dup_f32(X[b * K + k0 + kt + kk]);
        }
        __syncthreads();
        if (act) {
            const float* wp = W + (size_t)(k0 + kt) * N + n0;
#pragma unroll 4
            for (int kk = 0; kk < 64; ++kk) {
                ulonglong2 w2 = *(const ulonglong2*)wp;
                wp += N;
#pragma unroll
                for (int p = 0; p < 4; ++p) {
                    ulonglong2 xp = *(const ulonglong2*)&xs[kk][2 * p];
                    asm("fma.rn.f32x2 %0, %4, %6, %0;\n\t"
                        "fma.rn.f32x2 %1, %4, %7, %1;\n\t"
                        "fma.rn.f32x2 %2, %5, %6, %2;\n\t"
                        "fma.rn.f32x2 %3, %5, %7, %3;"
                        : "+l"(a01[2 * p]), "+l"(a23[2 * p]),
                          "+l"(a01[2 * p + 1]), "+l"(a23[2 * p + 1])
                        : "l"(xp.x), "l"(xp.y), "l"(w2.x), "l"(w2.y));
                }
            }
        }
    }
    if (act) {
#pragma unroll
        for (int b = 0; b < 8; ++b) {
            ulonglong2 o;
            o.x = a01[b];
            o.y = a23[b];
            *(ulonglong2*)(P + ((size_t)blockIdx.y * 8 + b) * N + n0) = o;
        }
    }
}

// ------------------------- fused QKV GEMM (concat N=6144), f32x2 ------------
__global__ void gemm_qkv(const float* __restrict__ wq,
                         const float* __restrict__ wk,
                         const float* __restrict__ wv, int kchunk) {
    __shared__ __align__(16) unsigned long long xs[64][8];
    const int K = DM;
    int nc = blockIdx.x * 1024 + threadIdx.x * 4;
    const float* W;
    int Nw, nl;
    if (nc < 4096)      { W = wq; Nw = 4096; nl = nc; }
    else if (nc < 5120) { W = wk; Nw = 1024; nl = nc - 4096; }
    else                { W = wv; Nw = 1024; nl = nc - 5120; }
    int k0 = blockIdx.y * kchunk;

    unsigned long long a01[8], a23[8];
#pragma unroll
    for (int b = 0; b < 8; ++b) { a01[b] = 0ull; a23[b] = 0ull; }

    for (int kt = 0; kt < kchunk; kt += 64) {
        __syncthreads();
        for (int i = threadIdx.x; i < 512; i += 256) {
            int kk = i >> 3, b = i & 7;
            xs[kk][b] = dup_f32(g_xn[b * K + k0 + kt + kk]);
        }
        __syncthreads();
        const float* wp = W + (size_t)(k0 + kt) * Nw + nl;
#pragma unroll 4
        for (int kk = 0; kk < 64; ++kk) {
            ulonglong2 w2 = *(const ulonglong2*)wp;
            wp += Nw;
#pragma unroll
            for (int p = 0; p < 4; ++p) {
                ulonglong2 xp = *(const ulonglong2*)&xs[kk][2 * p];
                asm("fma.rn.f32x2 %0, %4, %6, %0;\n\t"
                    "fma.rn.f32x2 %1, %4, %7, %1;\n\t"
                    "fma.rn.f32x2 %2, %5, %6, %2;\n\t"
                    "fma.rn.f32x2 %3, %5, %7, %3;"
                    : "+l"(a01[2 * p]), "+l"(a23[2 * p]),
                      "+l"(a01[2 * p + 1]), "+l"(a23[2 * p + 1])
                    : "l"(xp.x), "l"(xp.y), "l"(w2.x), "l"(w2.y));
            }
        }
    }
#pragma unroll
    for (int b = 0; b < 8; ++b) {
        ulonglong2 o;
        o.x = a01[b];
        o.y = a23[b];
        *(ulonglong2*)(g_PA + ((size_t)blockIdx.y * 8 + b) * 6144 + nc) = o;
    }
}

// ------------------------- fused w1|w3 GEMM (N=28672), f32x2 ----------------
__global__ void gemm_w13(const float* __restrict__ w1,
                         const float* __restrict__ w3, int kchunk) {
    __shared__ __align__(16) unsigned long long xs[64][8];
    const int K = DM;
    int nc = blockIdx.x * 1024 + threadIdx.x * 4;
    const float* W;
    float* P;
    int nl;
    if (nc < HID) { W = w1; P = g_PA; nl = nc; }
    else          { W = w3; P = g_PB; nl = nc - HID; }
    int k0 = blockIdx.y * kchunk;

    unsigned long long a01[8], a23[8];
#pragma unroll
    for (int b = 0; b < 8; ++b) { a01[b] = 0ull; a23[b] = 0ull; }

    for (int kt = 0; kt < kchunk; kt += 64) {
        __syncthreads();
        for (int i = threadIdx.x; i < 512; i += 256) {
            int kk = i >> 3, b = i & 7;
            xs[kk][b] = dup_f32(g_xn[b * K + k0 + kt + kk]);
        }
        __syncthreads();
        const float* wp = W + (size_t)(k0 + kt) * HID + nl;
#pragma unroll 4
        for (int kk = 0; kk < 64; ++kk) {
            ulonglong2 w2 = *(const ulonglong2*)wp;
            wp += HID;
#pragma unroll
            for (int p = 0; p < 4; ++p) {
                ulonglong2 xp = *(const ulonglong2*)&xs[kk][2 * p];
                asm("fma.rn.f32x2 %0, %4, %6, %0;\n\t"
                    "fma.rn.f32x2 %1, %4, %7, %1;\n\t"
                    "fma.rn.f32x2 %2, %5, %6, %2;\n\t"
                    "fma.rn.f32x2 %3, %5, %7, %3;"
                    : "+l"(a01[2 * p]), "+l"(a23[2 * p]),
                      "+l"(a01[2 * p + 1]), "+l"(a23[2 * p + 1])
                    : "l"(xp.x), "l"(xp.y), "l"(w2.x), "l"(w2.y));
            }
        }
    }
#pragma unroll
    for (int b = 0; b < 8; ++b) {
        ulonglong2 o;
        o.x = a01[b];
        o.y = a23[b];
        *(ulonglong2*)(P + ((size_t)blockIdx.y * 8 + b) * HID + nl) = o;
    }
}

// --------------- QKV combine (sum KS partials) + RoPE -----------------------
__global__ void qkv_finish(const int* __restrict__ sp) {
    int p = blockIdx.x * 256 + threadIdx.x; // 24576 pairs
    int b = p / 3072;
    int r = p - b * 3072;
    int c0 = r * 2;
    float s0 = 0.f, s1 = 0.f;
#pragma unroll 8
    for (int ks = 0; ks < 32; ++ks) {
        const float* pp = g_PA + ((size_t)ks * 8 + b) * 6144 + c0;
        s0 += pp[0];
        s1 += pp[1];
    }
    int pos = *sp;
    if (c0 < 4096) {
        int i = (c0 & 127) >> 1;
        float ifreq = powf(10000.0f, -(float)i * (1.0f / 64.0f));
        float ang = (float)pos * ifreq;
        float sn, cs;
        sincosf(ang, &sn, &cs);
        g_xq[b * 4096 + c0] = s0 * cs - s1 * sn;
        g_xq[b * 4096 + c0 + 1] = s0 * sn + s1 * cs;
    } else if (c0 < 5120) {
        int cc = c0 - 4096;
        int i = (cc & 127) >> 1;
        float ifreq = powf(10000.0f, -(float)i * (1.0f / 64.0f));
        float ang = (float)pos * ifreq;
        float sn, cs;
        sincosf(ang, &sn, &cs);
        g_xk[b * 1024 + cc] = s0 * cs - s1 * sn;
        g_xk[b * 1024 + cc + 1] = s0 * sn + s1 * cs;
    } else {
        int cc = c0 - 5120;
        g_xv[b * 1024 + cc] = s0;
        g_xv[b * 1024 + cc + 1] = s1;
    }
}

// --------------- attention partial: coalesced K/V ----------------------------
// block = 128 threads. Score phase: 4-lane groups per position (64B contiguous
// per LDG per row). V phase: warp-per-head, lanes = float4 over HD (512B/warp).
__global__ void attn_part(const float* __restrict__ ck,
                          const float* __restrict__ cv,
                          const int* __restrict__ sp) {
    int chunk = blockIdx.x, kv = blockIdx.y, b = blockIdx.z;
    int pos = *sp;
    int L = pos + 1;
    int s0 = chunk * ACH;
    int tid = threadIdx.x;

    __shared__ float4 qs[4][32];
    __shared__ float sc[4][ACH];
    __shared__ float Mh[4], Lh[4];

    {
        int h = tid >> 5, q = tid & 31;
        qs[h][q] = *(const float4*)(g_xq + (((b << 5) + (kv << 2) + h) << 7) + q * 4);
    }
    __syncthreads();

    int grp = tid >> 2;   // 0..31
    int lane4 = tid & 3;
    const float scale = 0.08838834764831845f;

#pragma unroll
    for (int pass = 0; pass < 4; ++pass) {
        int sl = pass * 32 + grp;
        int s = s0 + sl;
        float d0 = 0.f, d1 = 0.f, d2 = 0.f, d3 = 0.f;
        bool valid = s < L;
        if (valid) {
            const float4* kr = (s == pos)
                ? (const float4*)(g_xk + (((b << 3) + kv) << 7))
                : (const float4*)(ck + ((size_t)(b * MSEQ + s)) * (NKV * HD) + kv * HD);
#pragma unroll
            for (int q = 0; q < 8; ++q) {
                float4 k4 = kr[q * 4 + lane4];
                float4 qa = qs[0][q * 4 + lane4];
                float4 qb = qs[1][q * 4 + lane4];
                float4 qc = qs[2][q * 4 + lane4];
                float4 qd = qs[3][q * 4 + lane4];
                d0 += k4.x * qa.x + k4.y * qa.y + k4.z * qa.z + k4.w * qa.w;
                d1 += k4.x * qb.x + k4.y * qb.y + k4.z * qb.z + k4.w * qb.w;
                d2 += k4.x * qc.x + k4.y * qc.y + k4.z * qc.z + k4.w * qc.w;
                d3 += k4.x * qd.x + k4.y * qd.y + k4.z * qd.z + k4.w * qd.w;
            }
        }
#pragma unroll
        for (int o = 1; o <= 2; o <<= 1) {
            d0 += __shfl_xor_sync(0xffffffffu, d0, o);
            d1 += __shfl_xor_sync(0xffffffffu, d1, o);
            d2 += __shfl_xor_sync(0xffffffffu, d2, o);
            d3 += __shfl_xor_sync(0xffffffffu, d3, o);
        }
        if (lane4 == 0) {
            sc[0][sl] = valid ? d0 * scale : -1e30f;
            sc[1][sl] = valid ? d1 * scale : -1e30f;
            sc[2][sl] = valid ? d2 * scale : -1e30f;
            sc[3][sl] = valid ? d3 * scale : -1e30f;
        }
    }
    __syncthreads();

    int w = tid >> 5, l = tid & 31;
    {
        float v0 = sc[w][l], v1 = sc[w][l + 32], v2 = sc[w][l + 64], v3 = sc[w][l + 96];
        float m = fmaxf(fmaxf(v0, v1), fmaxf(v2, v3));
#pragma unroll
        for (int o = 16; o; o >>= 1) m = fmaxf(m, __shfl_xor_sync(0xffffffffu, m, o));
        float p0 = expf(v0 - m), p1 = expf(v1 - m), p2 = expf(v2 - m), p3 = expf(v3 - m);
        float sum = p0 + p1 + p2 + p3;
#pragma unroll
        for (int o = 16; o; o >>= 1) sum += __shfl_xor_sync(0xffffffffu, sum, o);
        sc[w][l] = p0; sc[w][l + 32] = p1; sc[w][l + 64] = p2; sc[w][l + 96] = p3;
        if (!l) { Mh[w] = m; Lh[w] = sum; }
    }
    __syncthreads();

    // V accumulation: warp w handles head (kv*4 + w); lane l = float4 over HD
    float4 a = make_float4(0.f, 0.f, 0.f, 0.f);
    int nc_ = pos - s0;
    if (nc_ > ACH) nc_ = ACH;
    if (nc_ < 0) nc_ = 0;
    const float4* vr = (const float4*)(cv + ((size_t)(b * MSEQ + s0)) * (NKV * HD) + kv * HD) + l;
#pragma unroll 4
    for (int ss = 0; ss < nc_; ++ss) {
        float4 v = vr[(size_t)ss * (NKV * HD / 4)];
        fma4(a, sc[w][ss], v);
    }
    if (pos >= s0 && pos < s0 + ACH) {
        float4 v = ((const float4*)(g_xv + (((b << 3) + kv) << 7)))[l];
        fma4(a, sc[w][pos - s0], v);
    }
    int h = (kv << 2) + w;
    *(float4*)(g_po + ((((size_t)(b << 5) + h) << 4) + chunk) * HD + l * 4) = a;
    if (!l) {
        g_pm[(((b << 5) + h) << 4) + chunk] = Mh[w];
        g_pl[(((b << 5) + h) << 4) + chunk] = Lh[w];
    }
}

// --------------- attention: combine chunk partials ---------------------------
__global__ void attn_combine() {
    int h = blockIdx.x, b = blockIdx.y, d = threadIdx.x; // 128 threads
    int base = ((b << 5) + h) << 4;
    float M = -1e30f;
#pragma unroll
    for (int c = 0; c < NCHK; ++c) M = fmaxf(M, g_pm[base + c]);
    float Ls = 0.f, o = 0.f;
#pragma unroll
    for (int c = 0; c < NCHK; ++c) {
        float w = expf(g_pm[base + c] - M);
        Ls += g_pl[base + c] * w;
        o += g_po[(size_t)(base + c) * HD + d] * w;
    }
    g_attn[((b << 5) + h) * HD + d] = o / Ls;
}

// --------------- combine partials + residual; stash colblock sumsq ----------
__global__ void finish_res(int KS) {
    int b = blockIdx.y;
    int c = blockIdx.x * 256 + threadIdx.x;
    float s = g_h[b * DM + c];
#pragma unroll 4
    for (int ks = 0; ks < KS; ++ks) s += g_PA[((size_t)ks * 8 + b) * DM + c];
    g_h[b * DM + c] = s;
    float tot = block_reduce_sum_256(s * s);
    if (threadIdx.x == 0) g_bsq[b * 16 + blockIdx.x] = tot;
}

__global__ void finish_norm(const float* __restrict__ gamma) {
    int b = blockIdx.y;
    int c = blockIdx.x * 256 + threadIdx.x;
    float sq = 0.f;
#pragma unroll
    for (int i = 0; i < 16; ++i) sq += g_bsq[b * 16 + i];
    float rn = rsqrtf(sq * (1.0f / DM));
    g_xn[b * DM + c] = g_h[b * DM + c] * rn * gamma[c];
}

// --------------- ffn gate: g = silu(x@w1) * (x@w3) ---------------------------
__global__ void ffn_act(int KS) {
    int b = blockIdx.y;
    int c = blockIdx.x * 256 + threadIdx.x;
    float s1 = 0.f, s3 = 0.f;
#pragma unroll 4
    for (int ks = 0; ks < KS; ++ks) {
        s1 += g_PA[((size_t)ks * 8 + b) * HID + c];
        s3 += g_PB[((size_t)ks * 8 + b) * HID + c];
    }
    float sig = 1.0f / (1.0f + expf(-s1));
    g_g[b * HID + c] = s1 * sig * s3;
}

// --------------- logits combine ----------------------------------------------
__global__ void wout_finish(float* __restrict__ out, int KS) {
    int b = blockIdx.y;
    int c = blockIdx.x * 256 + threadIdx.x;
    float s = 0.f;
#pragma unroll 4
    for (int ks = 0; ks < KS; ++ks) s += g_PA[((size_t)ks * 8 + b) * VOC + c];
    out[b * VOC + c] = s;
}

// ------------------------- launch --------------------------------------------
extern "C" void kernel_launch(void* const* d_in, const int* in_sizes, int n_in,
                              void* d_out, int out_size) {
    const int* tokens = (const int*)d_in[0];
    const int* sp = (const int*)d_in[1];
    const float* emb = (const float*)d_in[2];
    const float* g1 = (const float*)d_in[3];
    const float* g2 = (const float*)d_in[4];
    const float* gf = (const float*)d_in[5];
    const float* wq = (const float*)d_in[6];
    const float* wk = (const float*)d_in[7];
    const float* wv = (const float*)d_in[8];
    const float* wo = (const float*)d_in[9];
    const float* w1 = (const float*)d_in[10];
    const float* w2 = (const float*)d_in[11];
    const float* w3 = (const float*)d_in[12];
    const float* wout = (const float*)d_in[13];
    const float* ck = (const float*)d_in[14];
    const float* cv = (const float*)d_in[15];
    float* out = (float*)d_out;

    embed_norm<<<8, 256>>>(tokens, emb, g1);
    // QKV: KS=32, kchunk=128 -> 192 blocks
    gemm_qkv<<<dim3(6, 32), 256>>>(wq, wk, wv, 128);
    qkv_finish<<<96, 256>>>(sp);
    // attention: 16 chunks x 8 kv x 8 batch = 1024 blocks
    attn_part<<<dim3(NCHK, 8, 8), 128>>>(ck, cv, sp);
    attn_combine<<<dim3(32, 8), 128>>>();
    // wo: KS=64, kchunk=64 -> 256 blocks
    gemm8<1, 0><<<dim3(4, 64), 256>>>(wo, 4096, 4096, 64);
    finish_res<<<dim3(16, 8), 256>>>(64);
    finish_norm<<<dim3(16, 8), 256>>>(g2);
    // w1|w3 fused: KS=16, kchunk=256 -> 448 blocks
    gemm_w13<<<dim3(28, 16), 256>>>(w1, w3, 256);
    ffn_act<<<dim3(56, 8), 256>>>(16);
    // w2: KS=112, kchunk=128 -> 448 blocks
    gemm8<2, 0><<<dim3(4, 112), 256>>>(w2, 14336, 4096, 128);
    finish_res<<<dim3(16, 8), 256>>>(112);
    finish_norm<<<dim3(16, 8), 256>>>(gf);
    // w_out: KS=16, kchunk=256 -> 512 blocks
    gemm8<0, 0><<<dim3(32, 16), 256>>>(wout, 4096, 32000, 256);
    wout_finish<<<dim3(125, 8), 256>>>(out, 16);
}

// round 3
// speedup vs baseline: 1.2285x; 1.1032x over previous
#include <cuda_runtime.h>
#include <cuda_bf16.h>
#include <math.h>

// ---------------------------------------------------------------------------
// Llama-style decode step, BATCH=8, S=1. HBM-bound GEMVs (f32x2 FMA, X staged
// once per block, barrier-free stream loop) + flash-decode attention with
// minimum-traffic fully-sectored KV access.
// ---------------------------------------------------------------------------

#define DM 4096
#define NH 32
#define NKV 8
#define HD 128
#define HID 14336
#define VOC 32000
#define MSEQ 2048
#define B8 8
#define ACH 128   // attention chunk length
#define NCHK 16   // MSEQ / ACH

// ------------------------- scratch (device globals) -------------------------
__device__ float g_h[B8 * DM];
__device__ float g_xn[B8 * DM];
__device__ float g_xq[B8 * NH * HD];
__device__ float g_xk[B8 * NKV * HD];
__device__ float g_xv[B8 * NKV * HD];
__device__ float g_pm[B8 * NH * NCHK];
__device__ float g_pl[B8 * NH * NCHK];
__device__ float g_po[B8 * NH * NCHK * HD];
__device__ float g_attn[B8 * DM];
__device__ float g_g[B8 * HID];
__device__ float g_bsq[B8 * 16];
__device__ float g_PA[16 * 8 * 32000];
__device__ float g_PB[16 * 8 * 14336];

// ------------------------- helpers -------------------------
__device__ __forceinline__ void fma4(float4& a, float s, const float4& w) {
    a.x = fmaf(s, w.x, a.x);
    a.y = fmaf(s, w.y, a.y);
    a.z = fmaf(s, w.z, a.z);
    a.w = fmaf(s, w.w, a.w);
}

__device__ __forceinline__ float block_reduce_sum_256(float v) {
    __shared__ float red[8];
    int lane = threadIdx.x & 31, wid = threadIdx.x >> 5;
#pragma unroll
    for (int o = 16; o; o >>= 1) v += __shfl_xor_sync(0xffffffffu, v, o);
    if (!lane) red[wid] = v;
    __syncthreads();
    if (threadIdx.x == 0) {
        float t = 0.f;
#pragma unroll
        for (int w = 0; w < 8; ++w) t += red[w];
        red[0] = t;
    }
    __syncthreads();
    return red[0];
}

__device__ __forceinline__ unsigned long long dup_f32(float v) {
    unsigned long long pv;
    asm("mov.b64 %0, {%1, %1};" : "=l"(pv) : "f"(v));
    return pv;
}

// ------------------------- kernel 0: embed + rmsnorm(gamma1) ----------------
__global__ void embed_norm(const int* __restrict__ tokens,
                           const float* __restrict__ emb,
                           const float* __restrict__ gamma) {
    int b = blockIdx.x;
    int tok = tokens[b];
    const float* row = emb + (size_t)tok * DM;
    float loc[16];
    float sq = 0.f;
#pragma unroll
    for (int i = 0; i < 16; ++i) {
        float v = row[threadIdx.x + i * 256];
        loc[i] = v;
        sq += v * v;
    }
    float tot = block_reduce_sum_256(sq);
    float rn = rsqrtf(tot * (1.0f / DM));
#pragma unroll
    for (int i = 0; i < 16; ++i) {
        int c = threadIdx.x + i * 256;
        g_h[b * DM + c] = loc[i];
        g_xn[b * DM + c] = loc[i] * rn * gamma[c];
    }
}

// -------- GEMM inner macro: 1 LDG.128 + 4 LDS.128 + 16 FFMA2 per k ----------
#define GEMM_KSTEP(wp, stride)                                                 \
    {                                                                          \
        ulonglong2 w2 = *(const ulonglong2*)(wp);                              \
        (wp) += (stride);                                                      \
        _Pragma("unroll") for (int p = 0; p < 4; ++p) {                        \
            ulonglong2 xp = *(const ulonglong2*)&xs[kk][2 * p];                \
            asm("fma.rn.f32x2 %0, %4, %6, %0;\n\t"                             \
                "fma.rn.f32x2 %1, %4, %7, %1;\n\t"                             \
                "fma.rn.f32x2 %2, %5, %6, %2;\n\t"                             \
                "fma.rn.f32x2 %3, %5, %7, %3;"                                 \
                : "+l"(a01[2 * p]), "+l"(a23[2 * p]),                          \
                  "+l"(a01[2 * p + 1]), "+l"(a23[2 * p + 1])                   \
                : "l"(xp.x), "l"(xp.y), "l"(w2.x), "l"(w2.y));                 \
        }                                                                      \
    }

// ------------------------- generic split-K GEMM (M=8), f32x2 ----------------
// X staged ONCE per block; inner loop barrier-free.
// XSEL: 0 = g_xn, 1 = g_attn, 2 = g_g.  PSEL: 0 = g_PA, 1 = g_PB.
template <int XSEL, int PSEL>
__global__ __launch_bounds__(256) void gemm8(const float* __restrict__ W,
                                             int K, int N, int kchunk) {
    const float* X = (XSEL == 0) ? g_xn : (XSEL == 1) ? g_attn : g_g;
    float* P = (PSEL == 0) ? g_PA : g_PB;

    __shared__ __align__(16) unsigned long long xs[512][8];

    int k0 = blockIdx.y * kchunk;
#pragma unroll
    for (int b = 0; b < 8; ++b)
        for (int kk = threadIdx.x; kk < kchunk; kk += 256)
            xs[kk][b] = dup_f32(X[b * K + k0 + kk]);
    __syncthreads();

    int n0 = blockIdx.x * 1024 + threadIdx.x * 4;
    if (n0 >= N) return;

    unsigned long long a01[8], a23[8];
#pragma unroll
    for (int b = 0; b < 8; ++b) { a01[b] = 0ull; a23[b] = 0ull; }

    const float* wp = W + (size_t)k0 * N + n0;
#pragma unroll 4
    for (int kk = 0; kk < kchunk; ++kk) GEMM_KSTEP(wp, N);

#pragma unroll
    for (int b = 0; b < 8; ++b) {
        ulonglong2 o;
        o.x = a01[b];
        o.y = a23[b];
        *(ulonglong2*)(P + ((size_t)blockIdx.y * 8 + b) * N + n0) = o;
    }
}

// ------------------------- fused QKV GEMM (concat N=6144) -------------------
__global__ __launch_bounds__(256) void gemm_qkv(const float* __restrict__ wq,
                                                const float* __restrict__ wk,
                                                const float* __restrict__ wv,
                                                int kchunk) {
    __shared__ __align__(16) unsigned long long xs[512][8];
    const int K = DM;
    int k0 = blockIdx.y * kchunk;
#pragma unroll
    for (int b = 0; b < 8; ++b)
        for (int kk = threadIdx.x; kk < kchunk; kk += 256)
            xs[kk][b] = dup_f32(g_xn[b * K + k0 + kk]);
    __syncthreads();

    int nc = blockIdx.x * 1024 + threadIdx.x * 4;
    const float* W;
    int Nw, nl;
    if (nc < 4096)      { W = wq; Nw = 4096; nl = nc; }
    else if (nc < 5120) { W = wk; Nw = 1024; nl = nc - 4096; }
    else                { W = wv; Nw = 1024; nl = nc - 5120; }

    unsigned long long a01[8], a23[8];
#pragma unroll
    for (int b = 0; b < 8; ++b) { a01[b] = 0ull; a23[b] = 0ull; }

    const float* wp = W + (size_t)k0 * Nw + nl;
#pragma unroll 4
    for (int kk = 0; kk < kchunk; ++kk) GEMM_KSTEP(wp, Nw);

#pragma unroll
    for (int b = 0; b < 8; ++b) {
        ulonglong2 o;
        o.x = a01[b];
        o.y = a23[b];
        *(ulonglong2*)(g_PA + ((size_t)blockIdx.y * 8 + b) * 6144 + nc) = o;
    }
}

// ------------------------- fused w1|w3 GEMM (N=28672) -----------------------
__global__ __launch_bounds__(256) void gemm_w13(const float* __restrict__ w1,
                                                const float* __restrict__ w3,
                                                int kchunk) {
    __shared__ __align__(16) unsigned long long xs[512][8];
    const int K = DM;
    int k0 = blockIdx.y * kchunk;
#pragma unroll
    for (int b = 0; b < 8; ++b)
        for (int kk = threadIdx.x; kk < kchunk; kk += 256)
            xs[kk][b] = dup_f32(g_xn[b * K + k0 + kk]);
    __syncthreads();

    int nc = blockIdx.x * 1024 + threadIdx.x * 4;
    const float* W;
    float* P;
    int nl;
    if (nc < HID) { W = w1; P = g_PA; nl = nc; }
    else          { W = w3; P = g_PB; nl = nc - HID; }

    unsigned long long a01[8], a23[8];
#pragma unroll
    for (int b = 0; b < 8; ++b) { a01[b] = 0ull; a23[b] = 0ull; }

    const float* wp = W + (size_t)k0 * HID + nl;
#pragma unroll 4
    for (int kk = 0; kk < kchunk; ++kk) GEMM_KSTEP(wp, HID);

#pragma unroll
    for (int b = 0; b < 8; ++b) {
        ulonglong2 o;
        o.x = a01[b];
        o.y = a23[b];
        *(ulonglong2*)(P + ((size_t)blockIdx.y * 8 + b) * HID + nl) = o;
    }
}

// --------------- QKV combine (sum KS partials) + RoPE -----------------------
__global__ void qkv_finish(const int* __restrict__ sp) {
    int p = blockIdx.x * 256 + threadIdx.x; // 24576 pairs
    int b = p / 3072;
    int r = p - b * 3072;
    int c0 = r * 2;
    float s0 = 0.f, s1 = 0.f;
#pragma unroll 8
    for (int ks = 0; ks < 32; ++ks) {
        const float* pp = g_PA + ((size_t)ks * 8 + b) * 6144 + c0;
        s0 += pp[0];
        s1 += pp[1];
    }
    int pos = *sp;
    if (c0 < 4096) {
        int i = (c0 & 127) >> 1;
        float ifreq = powf(10000.0f, -(float)i * (1.0f / 64.0f));
        float ang = (float)pos * ifreq;
        float sn, cs;
        sincosf(ang, &sn, &cs);
        g_xq[b * 4096 + c0] = s0 * cs - s1 * sn;
        g_xq[b * 4096 + c0 + 1] = s0 * sn + s1 * cs;
    } else if (c0 < 5120) {
        int cc = c0 - 4096;
        int i = (cc & 127) >> 1;
        float ifreq = powf(10000.0f, -(float)i * (1.0f / 64.0f));
        float ang = (float)pos * ifreq;
        float sn, cs;
        sincosf(ang, &sn, &cs);
        g_xk[b * 1024 + cc] = s0 * cs - s1 * sn;
        g_xk[b * 1024 + cc + 1] = s0 * sn + s1 * cs;
    } else {
        int cc = c0 - 5120;
        g_xv[b * 1024 + cc] = s0;
        g_xv[b * 1024 + cc + 1] = s1;
    }
}

// --------------- attention partial, 256 threads per (chunk, kv, b) -----------
// Scores: one warp-LDG.128 = one full 512B K row (4 sectors, minimal).
// V: read once; each warp accumulates all 4 heads over strided positions.
__global__ __launch_bounds__(256) void attn_part(const float* __restrict__ ck,
                                                 const float* __restrict__ cv,
                                                 const int* __restrict__ sp) {
    int chunk = blockIdx.x, kv = blockIdx.y, b = blockIdx.z;
    int pos = *sp;
    int L = pos + 1;
    int s0 = chunk * ACH;
    int tid = threadIdx.x;
    int w = tid >> 5, l = tid & 31;

    __shared__ float4 qs[4][32];
    __shared__ float sc[4][ACH];
    __shared__ float Mh[4], Lh[4];
    __shared__ float4 vred[8][4][32];

    if (tid < 128) {
        int h = tid >> 5, q = tid & 31;
        qs[h][q] = *(const float4*)(g_xq + (((b << 5) + (kv << 2) + h) << 7) + q * 4);
    }
    __syncthreads();

    const float scale = 0.08838834764831845f; // 1/sqrt(128)
    const float4* kbase = (const float4*)(ck + ((size_t)b * MSEQ) * (NKV * HD) + kv * HD);

#pragma unroll 4
    for (int i = 0; i < ACH / 8; ++i) {
        int p = i * 8 + w;
        int s = s0 + p;
        float d0 = 0.f, d1 = 0.f, d2 = 0.f, d3 = 0.f;
        if (s < L) {
            float4 k4 = (s == pos)
                ? ((const float4*)(g_xk + (((b << 3) + kv) << 7)))[l]
                : kbase[(size_t)s * (NKV * HD / 4) + l];
            float4 qa = qs[0][l], qb = qs[1][l], qc = qs[2][l], qd = qs[3][l];
            d0 = k4.x * qa.x + k4.y * qa.y + k4.z * qa.z + k4.w * qa.w;
            d1 = k4.x * qb.x + k4.y * qb.y + k4.z * qb.z + k4.w * qb.w;
            d2 = k4.x * qc.x + k4.y * qc.y + k4.z * qc.z + k4.w * qc.w;
            d3 = k4.x * qd.x + k4.y * qd.y + k4.z * qd.z + k4.w * qd.w;
        }
#pragma unroll
        for (int o = 16; o; o >>= 1) {
            d0 += __shfl_xor_sync(0xffffffffu, d0, o);
            d1 += __shfl_xor_sync(0xffffffffu, d1, o);
            d2 += __shfl_xor_sync(0xffffffffu, d2, o);
            d3 += __shfl_xor_sync(0xffffffffu, d3, o);
        }
        if (l == 0) {
            bool valid = s < L;
            sc[0][p] = valid ? d0 * scale : -1e30f;
            sc[1][p] = valid ? d1 * scale : -1e30f;
            sc[2][p] = valid ? d2 * scale : -1e30f;
            sc[3][p] = valid ? d3 * scale : -1e30f;
        }
    }
    __syncthreads();

    if (w < 4) { // warp w = head w softmax over 128 scores
        float v0 = sc[w][l], v1 = sc[w][l + 32], v2 = sc[w][l + 64], v3 = sc[w][l + 96];
        float m = fmaxf(fmaxf(v0, v1), fmaxf(v2, v3));
#pragma unroll
        for (int o = 16; o; o >>= 1) m = fmaxf(m, __shfl_xor_sync(0xffffffffu, m, o));
        float p0 = expf(v0 - m), p1 = expf(v1 - m), p2 = expf(v2 - m), p3 = expf(v3 - m);
        float sum = p0 + p1 + p2 + p3;
#pragma unroll
        for (int o = 16; o; o >>= 1) sum += __shfl_xor_sync(0xffffffffu, sum, o);
        sc[w][l] = p0; sc[w][l + 32] = p1; sc[w][l + 64] = p2; sc[w][l + 96] = p3;
        if (!l) { Mh[w] = m; Lh[w] = sum; }
    }
    __syncthreads();

    // V pass: warp w covers positions w, w+8, ... ; all 4 heads at once.
    float4 a0 = make_float4(0.f, 0.f, 0.f, 0.f);
    float4 a1 = a0, a2 = a0, a3 = a0;
    int nc_ = pos - s0;
    if (nc_ > ACH) nc_ = ACH;
    if (nc_ < 0) nc_ = 0;
    const float4* vr = (const float4*)(cv + ((size_t)(b * MSEQ + s0)) * (NKV * HD) + kv * HD) + l;
    for (int ss = w; ss < nc_; ss += 8) {
        float4 v = vr[(size_t)ss * (NKV * HD / 4)];
        fma4(a0, sc[0][ss], v);
        fma4(a1, sc[1][ss], v);
        fma4(a2, sc[2][ss], v);
        fma4(a3, sc[3][ss], v);
    }
    int lp = pos - s0;
    if (lp >= 0 && lp < ACH && (lp & 7) == w) {
        float4 v = ((const float4*)(g_xv + (((b << 3) + kv) << 7)))[l];
        fma4(a0, sc[0][lp], v);
        fma4(a1, sc[1][lp], v);
        fma4(a2, sc[2][lp], v);
        fma4(a3, sc[3][lp], v);
    }
    vred[w][0][l] = a0;
    vred[w][1][l] = a1;
    vred[w][2][l] = a2;
    vred[w][3][l] = a3;
    __syncthreads();

    // combine 8 warp partials: thread -> (head h, float2 j)
    {
        int h = tid >> 6, j = tid & 63;
        float2 s2 = make_float2(0.f, 0.f);
#pragma unroll
        for (int ww = 0; ww < 8; ++ww) {
            float2 v = ((const float2*)vred[ww][h])[j];
            s2.x += v.x;
            s2.y += v.y;
        }
        int hg = (kv << 2) + h;
        *(float2*)(g_po + ((((size_t)(b << 5) + hg) << 4) + chunk) * HD + j * 2) = s2;
    }
    if (tid < 4) {
        int hg = (kv << 2) + tid;
        g_pm[(((b << 5) + hg) << 4) + chunk] = Mh[tid];
        g_pl[(((b << 5) + hg) << 4) + chunk] = Lh[tid];
    }
}

// --------------- attention: combine chunk partials ---------------------------
__global__ void attn_combine() {
    int h = blockIdx.x, b = blockIdx.y, d = threadIdx.x; // 128 threads
    int base = ((b << 5) + h) << 4;
    float M = -1e30f;
#pragma unroll
    for (int c = 0; c < NCHK; ++c) M = fmaxf(M, g_pm[base + c]);
    float Ls = 0.f, o = 0.f;
#pragma unroll
    for (int c = 0; c < NCHK; ++c) {
        float w = expf(g_pm[base + c] - M);
        Ls += g_pl[base + c] * w;
        o += g_po[(size_t)(base + c) * HD + d] * w;
    }
    g_attn[((b << 5) + h) * HD + d] = o / Ls;
}

// --------------- combine partials + residual; stash colblock sumsq ----------
__global__ void finish_res(int KS) {
    int b = blockIdx.y;
    int c = blockIdx.x * 256 + threadIdx.x;
    float s = g_h[b * DM + c];
#pragma unroll 4
    for (int ks = 0; ks < KS; ++ks) s += g_PA[((size_t)ks * 8 + b) * DM + c];
    g_h[b * DM + c] = s;
    float tot = block_reduce_sum_256(s * s);
    if (threadIdx.x == 0) g_bsq[b * 16 + blockIdx.x] = tot;
}

__global__ void finish_norm(const float* __restrict__ gamma) {
    int b = blockIdx.y;
    int c = blockIdx.x * 256 + threadIdx.x;
    float sq = 0.f;
#pragma unroll
    for (int i = 0; i < 16; ++i) sq += g_bsq[b * 16 + i];
    float rn = rsqrtf(sq * (1.0f / DM));
    g_xn[b * DM + c] = g_h[b * DM + c] * rn * gamma[c];
}

// --------------- ffn gate: g = silu(x@w1) * (x@w3) ---------------------------
__global__ void ffn_act(int KS) {
    int b = blockIdx.y;
    int c = blockIdx.x * 256 + threadIdx.x;
    float s1 = 0.f, s3 = 0.f;
#pragma unroll 4
    for (int ks = 0; ks < KS; ++ks) {
        s1 += g_PA[((size_t)ks * 8 + b) * HID + c];
        s3 += g_PB[((size_t)ks * 8 + b) * HID + c];
    }
    float sig = 1.0f / (1.0f + expf(-s1));
    g_g[b * HID + c] = s1 * sig * s3;
}

// --------------- logits combine ----------------------------------------------
__global__ void wout_finish(float* __restrict__ out, int KS) {
    int b = blockIdx.y;
    int c = blockIdx.x * 256 + threadIdx.x;
    float s = 0.f;
#pragma unroll 4
    for (int ks = 0; ks < KS; ++ks) s += g_PA[((size_t)ks * 8 + b) * VOC + c];
    out[b * VOC + c] = s;
}

// ------------------------- launch --------------------------------------------
extern "C" void kernel_launch(void* const* d_in, const int* in_sizes, int n_in,
                              void* d_out, int out_size) {
    const int* tokens = (const int*)d_in[0];
    const int* sp = (const int*)d_in[1];
    const float* emb = (const float*)d_in[2];
    const float* g1 = (const float*)d_in[3];
    const float* g2 = (const float*)d_in[4];
    const float* gf = (const float*)d_in[5];
    const float* wq = (const float*)d_in[6];
    const float* wk = (const float*)d_in[7];
    const float* wv = (const float*)d_in[8];
    const float* wo = (const float*)d_in[9];
    const float* w1 = (const float*)d_in[10];
    const float* w2 = (const float*)d_in[11];
    const float* w3 = (const float*)d_in[12];
    const float* wout = (const float*)d_in[13];
    const float* ck = (const float*)d_in[14];
    const float* cv = (const float*)d_in[15];
    float* out = (float*)d_out;

    embed_norm<<<8, 256>>>(tokens, emb, g1);
    // QKV: KS=32, kchunk=128 -> 192 blocks
    gemm_qkv<<<dim3(6, 32), 256>>>(wq, wk, wv, 128);
    qkv_finish<<<96, 256>>>(sp);
    // attention: 16 chunks x 8 kv x 8 batch = 1024 blocks x 256 thr
    attn_part<<<dim3(NCHK, 8, 8), 256>>>(ck, cv, sp);
    attn_combine<<<dim3(32, 8), 128>>>();
    // wo: KS=64, kchunk=64 -> 256 blocks
    gemm8<1, 0><<<dim3(4, 64), 256>>>(wo, 4096, 4096, 64);
    finish_res<<<dim3(16, 8), 256>>>(64);
    finish_norm<<<dim3(16, 8), 256>>>(g2);
    // w1|w3 fused: KS=16, kchunk=256 -> 448 blocks
    gemm_w13<<<dim3(28, 16), 256>>>(w1, w3, 256);
    ffn_act<<<dim3(56, 8), 256>>>(16);
    // w2: KS=112, kchunk=128 -> 448 blocks
    gemm8<2, 0><<<dim3(4, 112), 256>>>(w2, 14336, 4096, 128);
    finish_res<<<dim3(16, 8), 256>>>(112);
    finish_norm<<<dim3(16, 8), 256>>>(gf);
    // w_out: KS=16, kchunk=256 -> 512 blocks
    gemm8<0, 0><<<dim3(32, 16), 256>>>(wout, 4096, 32000, 256);
    wout_finish<<<dim3(125, 8), 256>>>(out, 16);
}

// round 4
// speedup vs baseline: 1.6021x; 1.3042x over previous
#include <cuda_runtime.h>
#include <cuda_bf16.h>
#include <math.h>

// ---------------------------------------------------------------------------
// Llama-style decode step, BATCH=8, S=1. HBM-bound GEMVs (f32x2 FMA, X staged
// once per block, barrier-free unroll-8 stream loop, exact-size smem) +
// flash-decode attention with minimum-traffic KV access.
// ---------------------------------------------------------------------------

#define DM 4096
#define NH 32
#define NKV 8
#define HD 128
#define HID 14336
#define VOC 32000
#define MSEQ 2048
#define B8 8
#define ACH 128   // attention chunk length
#define NCHK 16   // MSEQ / ACH

// ------------------------- scratch (device globals) -------------------------
__device__ float g_h[B8 * DM];
__device__ float g_xn[B8 * DM];
__device__ float g_xq[B8 * NH * HD];
__device__ float g_xk[B8 * NKV * HD];
__device__ float g_xv[B8 * NKV * HD];
__device__ float g_pm[B8 * NH * NCHK];
__device__ float g_pl[B8 * NH * NCHK];
__device__ float g_po[B8 * NH * NCHK * HD];
__device__ float g_attn[B8 * DM];
__device__ float g_g[B8 * HID];
__device__ float g_PA[16 * 8 * 32000];
__device__ float g_PB[16 * 8 * 14336];

// ------------------------- helpers -------------------------
__device__ __forceinline__ void fma4(float4& a, float s, const float4& w) {
    a.x = fmaf(s, w.x, a.x);
    a.y = fmaf(s, w.y, a.y);
    a.z = fmaf(s, w.z, a.z);
    a.w = fmaf(s, w.w, a.w);
}

__device__ __forceinline__ unsigned long long dup_f32(float v) {
    unsigned long long pv;
    asm("mov.b64 %0, {%1, %1};" : "=l"(pv) : "f"(v));
    return pv;
}

// -------- GEMM inner macro: 1 LDG.128 + 4 LDS.128 + 16 FFMA2 per k ----------
#define GEMM_KSTEP(wp, stride)                                                 \
    {                                                                          \
        ulonglong2 w2 = __ldg((const ulonglong2*)(wp));                        \
        (wp) += (stride);                                                      \
        _Pragma("unroll") for (int p = 0; p < 4; ++p) {                        \
            ulonglong2 xp = *(const ulonglong2*)&xs[kk][2 * p];                \
            asm("fma.rn.f32x2 %0, %4, %6, %0;\n\t"                             \
                "fma.rn.f32x2 %1, %4, %7, %1;\n\t"                             \
                "fma.rn.f32x2 %2, %5, %6, %2;\n\t"                             \
                "fma.rn.f32x2 %3, %5, %7, %3;"                                 \
                : "+l"(a01[2 * p]), "+l"(a23[2 * p]),                          \
                  "+l"(a01[2 * p + 1]), "+l"(a23[2 * p + 1])                   \
                : "l"(xp.x), "l"(xp.y), "l"(w2.x), "l"(w2.y));                 \
        }                                                                      \
    }

// ------------------------- kernel 0: embed + rmsnorm(gamma1) ----------------
__global__ void embed_norm(const int* __restrict__ tokens,
                           const float* __restrict__ emb,
                           const float* __restrict__ gamma) {
    __shared__ float red[8];
    int b = blockIdx.x;
    int tok = tokens[b];
    const float* row = emb + (size_t)tok * DM;
    float loc[16];
    float sq = 0.f;
#pragma unroll
    for (int i = 0; i < 16; ++i) {
        float v = row[threadIdx.x + i * 256];
        loc[i] = v;
        sq += v * v;
    }
    int lane = threadIdx.x & 31, wid = threadIdx.x >> 5;
#pragma unroll
    for (int o = 16; o; o >>= 1) sq += __shfl_xor_sync(0xffffffffu, sq, o);
    if (!lane) red[wid] = sq;
    __syncthreads();
    float tot = 0.f;
#pragma unroll
    for (int w = 0; w < 8; ++w) tot += red[w];
    float rn = rsqrtf(tot * (1.0f / DM));
#pragma unroll
    for (int i = 0; i < 16; ++i) {
        int c = threadIdx.x + i * 256;
        g_h[b * DM + c] = loc[i];
        g_xn[b * DM + c] = loc[i] * rn * gamma[c];
    }
}

// ------------------------- generic split-K GEMM (M=8), f32x2 ----------------
// XSEL: 0 = g_xn, 1 = g_attn, 2 = g_g.  PSEL: 0 = g_PA, 1 = g_PB.
template <int XSEL, int PSEL, int KCH>
__global__ __launch_bounds__(256, 3) void gemm8(const float* __restrict__ W,
                                                int K, int N) {
    const float* X = (XSEL == 0) ? g_xn : (XSEL == 1) ? g_attn : g_g;
    float* P = (PSEL == 0) ? g_PA : g_PB;

    __shared__ __align__(16) unsigned long long xs[KCH][8];

    int k0 = blockIdx.y * KCH;
#pragma unroll
    for (int b = 0; b < 8; ++b)
        for (int kk = threadIdx.x; kk < KCH; kk += 256)
            xs[kk][b] = dup_f32(X[b * K + k0 + kk]);
    __syncthreads();

    int n0 = blockIdx.x * 1024 + threadIdx.x * 4;
    if (n0 >= N) return;

    unsigned long long a01[8], a23[8];
#pragma unroll
    for (int b = 0; b < 8; ++b) { a01[b] = 0ull; a23[b] = 0ull; }

    const float* wp = W + (size_t)k0 * N + n0;
#pragma unroll 8
    for (int kk = 0; kk < KCH; ++kk) GEMM_KSTEP(wp, N);

#pragma unroll
    for (int b = 0; b < 8; ++b) {
        ulonglong2 o;
        o.x = a01[b];
        o.y = a23[b];
        *(ulonglong2*)(P + ((size_t)blockIdx.y * 8 + b) * N + n0) = o;
    }
}

// ------------------------- fused QKV GEMM (concat N=6144) -------------------
__global__ __launch_bounds__(256, 3) void gemm_qkv(const float* __restrict__ wq,
                                                   const float* __restrict__ wk,
                                                   const float* __restrict__ wv) {
    const int KCH = 128;
    __shared__ __align__(16) unsigned long long xs[KCH][8];
    const int K = DM;
    int k0 = blockIdx.y * KCH;
#pragma unroll
    for (int b = 0; b < 8; ++b)
        for (int kk = threadIdx.x; kk < KCH; kk += 256)
            xs[kk][b] = dup_f32(g_xn[b * K + k0 + kk]);
    __syncthreads();

    int nc = blockIdx.x * 1024 + threadIdx.x * 4;
    const float* W;
    int Nw, nl;
    if (nc < 4096)      { W = wq; Nw = 4096; nl = nc; }
    else if (nc < 5120) { W = wk; Nw = 1024; nl = nc - 4096; }
    else                { W = wv; Nw = 1024; nl = nc - 5120; }

    unsigned long long a01[8], a23[8];
#pragma unroll
    for (int b = 0; b < 8; ++b) { a01[b] = 0ull; a23[b] = 0ull; }

    const float* wp = W + (size_t)k0 * Nw + nl;
#pragma unroll 8
    for (int kk = 0; kk < KCH; ++kk) GEMM_KSTEP(wp, Nw);

#pragma unroll
    for (int b = 0; b < 8; ++b) {
        ulonglong2 o;
        o.x = a01[b];
        o.y = a23[b];
        *(ulonglong2*)(g_PA + ((size_t)blockIdx.y * 8 + b) * 6144 + nc) = o;
    }
}

// ------------------------- fused w1|w3 GEMM (N=28672) -----------------------
__global__ __launch_bounds__(256, 3) void gemm_w13(const float* __restrict__ w1,
                                                   const float* __restrict__ w3) {
    const int KCH = 256;
    __shared__ __align__(16) unsigned long long xs[KCH][8];
    const int K = DM;
    int k0 = blockIdx.y * KCH;
#pragma unroll
    for (int b = 0; b < 8; ++b)
        for (int kk = threadIdx.x; kk < KCH; kk += 256)
            xs[kk][b] = dup_f32(g_xn[b * K + k0 + kk]);
    __syncthreads();

    int nc = blockIdx.x * 1024 + threadIdx.x * 4;
    const float* W;
    float* P;
    int nl;
    if (nc < HID) { W = w1; P = g_PA; nl = nc; }
    else          { W = w3; P = g_PB; nl = nc - HID; }

    unsigned long long a01[8], a23[8];
#pragma unroll
    for (int b = 0; b < 8; ++b) { a01[b] = 0ull; a23[b] = 0ull; }

    const float* wp = W + (size_t)k0 * HID + nl;
#pragma unroll 8
    for (int kk = 0; kk < KCH; ++kk) GEMM_KSTEP(wp, HID);

#pragma unroll
    for (int b = 0; b < 8; ++b) {
        ulonglong2 o;
        o.x = a01[b];
        o.y = a23[b];
        *(ulonglong2*)(P + ((size_t)blockIdx.y * 8 + b) * HID + nl) = o;
    }
}

// --------------- QKV combine (sum 32 partials) + RoPE, float4 ---------------
__global__ void qkv_finish(const int* __restrict__ sp) {
    int p = blockIdx.x * 256 + threadIdx.x; // 12288 float4 slots
    int b = p / 1536;
    int r = p - b * 1536;
    int c0 = r * 4;
    float4 s = make_float4(0.f, 0.f, 0.f, 0.f);
#pragma unroll 8
    for (int ks = 0; ks < 32; ++ks) {
        float4 v = *(const float4*)(g_PA + ((size_t)ks * 8 + b) * 6144 + c0);
        s.x += v.x; s.y += v.y; s.z += v.z; s.w += v.w;
    }
    int pos = *sp;
    if (c0 < 5120) {
        int cc = (c0 < 4096) ? c0 : c0 - 4096;
        int i0 = (cc & 127) >> 1;       // pair index of (x,y)
        float if0 = powf(10000.0f, -(float)i0 * (1.0f / 64.0f));
        float if1 = powf(10000.0f, -(float)(i0 + 1) * (1.0f / 64.0f));
        float sn0, cs0, sn1, cs1;
        sincosf((float)pos * if0, &sn0, &cs0);
        sincosf((float)pos * if1, &sn1, &cs1);
        float4 o;
        o.x = s.x * cs0 - s.y * sn0;
        o.y = s.x * sn0 + s.y * cs0;
        o.z = s.z * cs1 - s.w * sn1;
        o.w = s.z * sn1 + s.w * cs1;
        if (c0 < 4096)
            *(float4*)(g_xq + b * 4096 + c0) = o;
        else
            *(float4*)(g_xk + b * 1024 + (c0 - 4096)) = o;
    } else {
        *(float4*)(g_xv + b * 1024 + (c0 - 5120)) = s;
    }
}

// --------------- attention partial, 256 threads per (chunk, kv, b) -----------
__global__ __launch_bounds__(256) void attn_part(const float* __restrict__ ck,
                                                 const float* __restrict__ cv,
                                                 const int* __restrict__ sp) {
    int chunk = blockIdx.x, kv = blockIdx.y, b = blockIdx.z;
    int pos = *sp;
    int L = pos + 1;
    int s0 = chunk * ACH;
    int tid = threadIdx.x;
    int w = tid >> 5, l = tid & 31;

    __shared__ float4 qs[4][32];
    __shared__ float4 sc4[ACH];       // (p0,p1,p2,p3) per position
    __shared__ float Mh[4], Lh[4];
    __shared__ float4 vred[8][4][32];

    if (tid < 128) {
        int h = tid >> 5, q = tid & 31;
        qs[h][q] = *(const float4*)(g_xq + (((b << 5) + (kv << 2) + h) << 7) + q * 4);
    }
    __syncthreads();

    const float scale = 0.08838834764831845f; // 1/sqrt(128)
    const float4* kbase = (const float4*)(ck + ((size_t)b * MSEQ) * (NKV * HD) + kv * HD);

#pragma unroll 4
    for (int i = 0; i < ACH / 8; ++i) {
        int p = i * 8 + w;
        int s = s0 + p;
        float d0 = 0.f, d1 = 0.f, d2 = 0.f, d3 = 0.f;
        if (s < L) {
            float4 k4 = (s == pos)
                ? ((const float4*)(g_xk + (((b << 3) + kv) << 7)))[l]
                : kbase[(size_t)s * (NKV * HD / 4) + l];
            float4 qa = qs[0][l], qb = qs[1][l], qc = qs[2][l], qd = qs[3][l];
            d0 = k4.x * qa.x + k4.y * qa.y + k4.z * qa.z + k4.w * qa.w;
            d1 = k4.x * qb.x + k4.y * qb.y + k4.z * qb.z + k4.w * qb.w;
            d2 = k4.x * qc.x + k4.y * qc.y + k4.z * qc.z + k4.w * qc.w;
            d3 = k4.x * qd.x + k4.y * qd.y + k4.z * qd.z + k4.w * qd.w;
        }
#pragma unroll
        for (int o = 16; o; o >>= 1) {
            d0 += __shfl_xor_sync(0xffffffffu, d0, o);
            d1 += __shfl_xor_sync(0xffffffffu, d1, o);
            d2 += __shfl_xor_sync(0xffffffffu, d2, o);
            d3 += __shfl_xor_sync(0xffffffffu, d3, o);
        }
        if (l == 0) {
            bool valid = s < L;
            sc4[p] = valid ? make_float4(d0 * scale, d1 * scale, d2 * scale, d3 * scale)
                           : make_float4(-1e30f, -1e30f, -1e30f, -1e30f);
        }
    }
    __syncthreads();

    if (w < 4) { // warp w = head w softmax over 128 scores (component w)
        const float* scf = (const float*)sc4;
        float v0 = scf[l * 4 + w], v1 = scf[(l + 32) * 4 + w],
              v2 = scf[(l + 64) * 4 + w], v3 = scf[(l + 96) * 4 + w];
        float m = fmaxf(fmaxf(v0, v1), fmaxf(v2, v3));
#pragma unroll
        for (int o = 16; o; o >>= 1) m = fmaxf(m, __shfl_xor_sync(0xffffffffu, m, o));
        float p0 = expf(v0 - m), p1 = expf(v1 - m), p2 = expf(v2 - m), p3 = expf(v3 - m);
        float sum = p0 + p1 + p2 + p3;
#pragma unroll
        for (int o = 16; o; o >>= 1) sum += __shfl_xor_sync(0xffffffffu, sum, o);
        float* scw = (float*)sc4;
        scw[l * 4 + w] = p0;
        scw[(l + 32) * 4 + w] = p1;
        scw[(l + 64) * 4 + w] = p2;
        scw[(l + 96) * 4 + w] = p3;
        if (!l) { Mh[w] = m; Lh[w] = sum; }
    }
    __syncthreads();

    // V pass: warp w covers positions w, w+8, ... ; one LDS.128 per position.
    float4 a0 = make_float4(0.f, 0.f, 0.f, 0.f);
    float4 a1 = a0, a2 = a0, a3 = a0;
    int nc_ = pos - s0;
    if (nc_ > ACH) nc_ = ACH;
    if (nc_ < 0) nc_ = 0;
    const float4* vr = (const float4*)(cv + ((size_t)(b * MSEQ + s0)) * (NKV * HD) + kv * HD) + l;
#pragma unroll 4
    for (int ss = w; ss < nc_; ss += 8) {
        float4 v = vr[(size_t)ss * (NKV * HD / 4)];
        float4 p = sc4[ss];
        fma4(a0, p.x, v);
        fma4(a1, p.y, v);
        fma4(a2, p.z, v);
        fma4(a3, p.w, v);
    }
    int lp = pos - s0;
    if (lp >= 0 && lp < ACH && (lp & 7) == w) {
        float4 v = ((const float4*)(g_xv + (((b << 3) + kv) << 7)))[l];
        float4 p = sc4[lp];
        fma4(a0, p.x, v);
        fma4(a1, p.y, v);
        fma4(a2, p.z, v);
        fma4(a3, p.w, v);
    }
    vred[w][0][l] = a0;
    vred[w][1][l] = a1;
    vred[w][2][l] = a2;
    vred[w][3][l] = a3;
    __syncthreads();

    {
        int h = tid >> 6, j = tid & 63;
        float2 s2 = make_float2(0.f, 0.f);
#pragma unroll
        for (int ww = 0; ww < 8; ++ww) {
            float2 v = ((const float2*)vred[ww][h])[j];
            s2.x += v.x;
            s2.y += v.y;
        }
        int hg = (kv << 2) + h;
        *(float2*)(g_po + ((((size_t)(b << 5) + hg) << 4) + chunk) * HD + j * 2) = s2;
    }
    if (tid < 4) {
        int hg = (kv << 2) + tid;
        g_pm[(((b << 5) + hg) << 4) + chunk] = Mh[tid];
        g_pl[(((b << 5) + hg) << 4) + chunk] = Lh[tid];
    }
}

// --------------- attention: combine chunk partials ---------------------------
__global__ void attn_combine() {
    int h = blockIdx.x, b = blockIdx.y, d = threadIdx.x; // 128 threads
    int base = ((b << 5) + h) << 4;
    float M = -1e30f;
#pragma unroll
    for (int c = 0; c < NCHK; ++c) M = fmaxf(M, g_pm[base + c]);
    float Ls = 0.f, o = 0.f;
#pragma unroll
    for (int c = 0; c < NCHK; ++c) {
        float w = expf(g_pm[base + c] - M);
        Ls += g_pl[base + c] * w;
        o += g_po[(size_t)(base + c) * HD + d] * w;
    }
    g_attn[((b << 5) + h) * HD + d] = o / Ls;
}

// --------- fused: combine partials + residual + rmsnorm (one launch) --------
// 8 blocks (one per batch) x 1024 threads, 4 contiguous cols per thread.
__global__ __launch_bounds__(1024) void fused_res_norm(const float* __restrict__ gamma,
                                                       int KS) {
    __shared__ float red[32];
    int b = blockIdx.x;
    int c = threadIdx.x * 4;
    float4 s = *(const float4*)(g_h + b * DM + c);
#pragma unroll 4
    for (int ks = 0; ks < KS; ++ks) {
        float4 v = *(const float4*)(g_PA + ((size_t)ks * 8 + b) * DM + c);
        s.x += v.x; s.y += v.y; s.z += v.z; s.w += v.w;
    }
    *(float4*)(g_h + b * DM + c) = s;
    float sq = s.x * s.x + s.y * s.y + s.z * s.z + s.w * s.w;
    int lane = threadIdx.x & 31, wid = threadIdx.x >> 5;
#pragma unroll
    for (int o = 16; o; o >>= 1) sq += __shfl_xor_sync(0xffffffffu, sq, o);
    if (!lane) red[wid] = sq;
    __syncthreads();
    if (threadIdx.x < 32) {
        float t = red[threadIdx.x];
#pragma unroll
        for (int o = 16; o; o >>= 1) t += __shfl_xor_sync(0xffffffffu, t, o);
        if (!threadIdx.x) red[0] = t;
    }
    __syncthreads();
    float rn = rsqrtf(red[0] * (1.0f / DM));
    float4 gm = *(const float4*)(gamma + c);
    float4 o;
    o.x = s.x * rn * gm.x;
    o.y = s.y * rn * gm.y;
    o.z = s.z * rn * gm.z;
    o.w = s.w * rn * gm.w;
    *(float4*)(g_xn + b * DM + c) = o;
}

// --------------- ffn gate: g = silu(x@w1) * (x@w3), float4 -------------------
__global__ void ffn_act(int KS) {
    int b = blockIdx.y;
    int c = (blockIdx.x * 256 + threadIdx.x) * 4;
    float4 s1 = make_float4(0.f, 0.f, 0.f, 0.f), s3 = s1;
#pragma unroll 4
    for (int ks = 0; ks < KS; ++ks) {
        float4 v1 = *(const float4*)(g_PA + ((size_t)ks * 8 + b) * HID + c);
        float4 v3 = *(const float4*)(g_PB + ((size_t)ks * 8 + b) * HID + c);
        s1.x += v1.x; s1.y += v1.y; s1.z += v1.z; s1.w += v1.w;
        s3.x += v3.x; s3.y += v3.y; s3.z += v3.z; s3.w += v3.w;
    }
    float4 o;
    o.x = s1.x / (1.0f + expf(-s1.x)) * s3.x;
    o.y = s1.y / (1.0f + expf(-s1.y)) * s3.y;
    o.z = s1.z / (1.0f + expf(-s1.z)) * s3.z;
    o.w = s1.w / (1.0f + expf(-s1.w)) * s3.w;
    *(float4*)(g_g + b * HID + c) = o;
}

// --------------- logits combine, float4 --------------------------------------
__global__ void wout_finish(float* __restrict__ out, int KS) {
    int b = blockIdx.y;
    int c4 = blockIdx.x * 256 + threadIdx.x;
    if (c4 >= VOC / 4) return;
    int c = c4 * 4;
    float4 s = make_float4(0.f, 0.f, 0.f, 0.f);
#pragma unroll 4
    for (int ks = 0; ks < KS; ++ks) {
        float4 v = *(const float4*)(g_PA + ((size_t)ks * 8 + b) * VOC + c);
        s.x += v.x; s.y += v.y; s.z += v.z; s.w += v.w;
    }
    *(float4*)(out + b * VOC + c) = s;
}

// ------------------------- launch --------------------------------------------
extern "C" void kernel_launch(void* const* d_in, const int* in_sizes, int n_in,
                              void* d_out, int out_size) {
    const int* tokens = (const int*)d_in[0];
    const int* sp = (const int*)d_in[1];
    const float* emb = (const float*)d_in[2];
    const float* g1 = (const float*)d_in[3];
    const float* g2 = (const float*)d_in[4];
    const float* gf = (const float*)d_in[5];
    const float* wq = (const float*)d_in[6];
    const float* wk = (const float*)d_in[7];
    const float* wv = (const float*)d_in[8];
    const float* wo = (const float*)d_in[9];
    const float* w1 = (const float*)d_in[10];
    const float* w2 = (const float*)d_in[11];
    const float* w3 = (const float*)d_in[12];
    const float* wout = (const float*)d_in[13];
    const float* ck = (const float*)d_in[14];
    const float* cv = (const float*)d_in[15];
    float* out = (float*)d_out;

    embed_norm<<<8, 256>>>(tokens, emb, g1);
    // QKV: KS=32, kchunk=128 -> 192 blocks
    gemm_qkv<<<dim3(6, 32), 256>>>(wq, wk, wv);
    qkv_finish<<<48, 256>>>(sp);
    // attention: 16 chunks x 8 kv x 8 batch = 1024 blocks x 256 thr
    attn_part<<<dim3(NCHK, 8, 8), 256>>>(ck, cv, sp);
    attn_combine<<<dim3(32, 8), 128>>>();
    // wo: KS=64, kchunk=64 -> 256 blocks
    gemm8<1, 0, 64><<<dim3(4, 64), 256>>>(wo, 4096, 4096);
    fused_res_norm<<<8, 1024>>>(g2, 64);
    // w1|w3 fused: KS=16, kchunk=256 -> 448 blocks
    gemm_w13<<<dim3(28, 16), 256>>>(w1, w3);
    ffn_act<<<dim3(14, 8), 256>>>(16);
    // w2: KS=112, kchunk=128 -> 448 blocks
    gemm8<2, 0, 128><<<dim3(4, 112), 256>>>(w2, 14336, 4096);
    fused_res_norm<<<8, 1024>>>(gf, 112);
    // w_out: KS=16, kchunk=256 -> 512 blocks
    gemm8<0, 0, 256><<<dim3(32, 16), 256>>>(wout, 4096, 32000);
    wout_finish<<<dim3(32, 8), 256>>>(out, 16);
}